// round 6
// baseline (speedup 1.0000x reference)
#include <cuda_runtime.h>
#include <cuda_bf16.h>
#include <cstdint>

// ---------------- problem constants ----------------
#define M_CANDS 131072
#define N_ROWS  2048
#define DIM     64
#define KSEL    11                 // k+1 smallest; smallest (self) dropped later

// ---------------- tiling ----------------
#define PARTS    16                      // candidate partitions
#define ROWS_CTA 256                     // x rows per CTA (16 warps x 16 rows)
#define ROWTILES (N_ROWS / ROWS_CTA)     // 8
#define CPART    (M_CANDS / PARTS)       // 8192 candidates per CTA
#define TN       256                     // candidates per smem tile
#define NT       (CPART / TN)            // 32 tiles
#define THREADS  512
#define TILE_BYTES (TN * 128)            // 32768
#define BN_BYTES   (TN * 4)              // 1024

// ---------------- smem layout (bytes) ----------------
#define SM_MBAR  0                       // 3 mbarriers
#define SM_B     1024
#define SM_BN    (SM_B + 3 * TILE_BYTES)          // 99328
#define SMEM_TOTAL (SM_BN + 3 * BN_BYTES)         // 102400

#define POS_INF __int_as_float(0x7f800000)
#define NEG_INF __int_as_float(0xff800000)

// ---------------- device globals (allocation-free scratch) ----------------
__device__ __align__(128) __nv_bfloat16 g_bbf[(size_t)M_CANDS * DIM]; // -2*buf, bf16, tile-swizzled
__device__ __align__(16)  __nv_bfloat16 g_xbf[(size_t)N_ROWS * DIM];
__device__ __align__(16)  float g_bnorm[M_CANDS];
__device__ __align__(16)  float g_xnorm[N_ROWS];
__device__ __align__(16)  float g_partial[(size_t)N_ROWS * PARTS * KSEL];

// ---------------- helpers ----------------
__device__ __forceinline__ uint32_t smem_u32(const void* p) {
    return (uint32_t)__cvta_generic_to_shared(p);
}
#define SWZ128(off) ((off) ^ (((off) >> 3) & 0x70))

#define MBARRIER_INIT(mbar, cnt) \
    asm volatile("mbarrier.init.shared.b64 [%0], %1;" \
                 :: "r"((uint32_t)(mbar)), "r"((uint32_t)(cnt)) : "memory")
#define MBARRIER_EXPECT_TX(mbar, bytes) \
    asm volatile("mbarrier.arrive.expect_tx.shared.b64 _, [%0], %1;" \
                 :: "r"((uint32_t)(mbar)), "r"((uint32_t)(bytes)) : "memory")
#define MBARRIER_WAIT_PARITY(mbar, parity) do {                                   \
    uint32_t _m = (uint32_t)(mbar); uint32_t _p = (uint32_t)(parity);             \
    asm volatile("{\n\t.reg .pred P1;\n\t"                                        \
        "WAIT_LOOP_%=:\n\t"                                                       \
        "mbarrier.try_wait.parity.acquire.cta.shared::cta.b64 P1, [%0], %1, 0x989680;\n\t" \
        "@P1 bra.uni WAIT_DONE_%=;\n\t"                                           \
        "bra.uni WAIT_LOOP_%=;\n\t"                                               \
        "WAIT_DONE_%=:\n\t}" :: "r"(_m), "r"(_p) : "memory");                     \
} while (0)

__device__ __forceinline__ void bulk_g2s(uint32_t dst, const void* src,
                                         uint32_t bytes, uint32_t mbar) {
    asm volatile(
        "cp.async.bulk.shared::cluster.global.mbarrier::complete_tx::bytes "
        "[%0], [%1], %2, [%3];"
        :: "r"(dst), "l"(__cvta_generic_to_global(src)), "r"(bytes), "r"(mbar)
        : "memory");
}

// ldmatrix x4: 4 8x8 b16 matrices; lane supplies one 16B row address
__device__ __forceinline__ void ldsm4(uint32_t* r, uint32_t addr) {
    asm volatile("ldmatrix.sync.aligned.m8n8.x4.shared.b16 {%0,%1,%2,%3}, [%4];"
                 : "=r"(r[0]), "=r"(r[1]), "=r"(r[2]), "=r"(r[3]) : "r"(addr));
}

// m16n8k16 row.col bf16 -> f32, D += A*B (D aliases C)
__device__ __forceinline__ void mma16816(float c[4], const uint32_t a[4],
                                         uint32_t b0, uint32_t b1) {
    asm volatile(
        "mma.sync.aligned.m16n8k16.row.col.f32.bf16.bf16.f32 "
        "{%0,%1,%2,%3}, {%4,%5,%6,%7}, {%8,%9}, {%0,%1,%2,%3};"
        : "+f"(c[0]), "+f"(c[1]), "+f"(c[2]), "+f"(c[3])
        : "r"(a[0]), "r"(a[1]), "r"(a[2]), "r"(a[3]), "r"(b0), "r"(b1));
}

// keep h[0..10] ascending; caller ensured v < h[10]
__device__ __forceinline__ void bubble_insert(float* h, float v) {
#pragma unroll
    for (int j = 0; j < KSEL; ++j) {
        float lo = fminf(h[j], v);
        v = fmaxf(h[j], v);
        h[j] = lo;
    }
}

// merge my ascending 11-list with lane^mask's; keep 11 smallest, ascending
__device__ __forceinline__ void merge11(float h[KSEL], int mask) {
    float b[KSEL];
#pragma unroll
    for (int j = 0; j < KSEL; ++j) b[j] = __shfl_xor_sync(0xffffffffu, h[j], mask);
    float c[16];
#pragma unroll
    for (int i = 0; i < 5; ++i) c[i] = NEG_INF;
#pragma unroll
    for (int i = 0; i < KSEL; ++i) c[5 + i] = fminf(h[i], b[10 - i]);
#pragma unroll
    for (int d = 8; d >= 1; d >>= 1)
#pragma unroll
        for (int i = 0; i < 16; ++i)
            if ((i & d) == 0) {
                float lo = fminf(c[i], c[i | d]);
                float hi = fmaxf(c[i], c[i | d]);
                c[i] = lo; c[i | d] = hi;
            }
#pragma unroll
    for (int i = 0; i < KSEL; ++i) h[i] = c[5 + i];
}

// ---------------- prep kernels ----------------
__global__ void prep_buf_kernel(const float* __restrict__ buf) {
    int c = blockIdx.x * 256 + threadIdx.x;
    const float4* s = reinterpret_cast<const float4*>(buf) + (size_t)c * 16;
    uint4 pk[8];
    uint32_t* pw = reinterpret_cast<uint32_t*>(pk);
    float n = 0.f;
#pragma unroll
    for (int q = 0; q < 16; ++q) {
        float4 v = s[q];
        n = fmaf(v.x, v.x, n); n = fmaf(v.y, v.y, n);
        n = fmaf(v.z, v.z, n); n = fmaf(v.w, v.w, n);
        __nv_bfloat162 a = __floats2bfloat162_rn(-2.f * v.x, -2.f * v.y);
        __nv_bfloat162 b = __floats2bfloat162_rn(-2.f * v.z, -2.f * v.w);
        pw[2 * q]     = reinterpret_cast<uint32_t&>(a);
        pw[2 * q + 1] = reinterpret_cast<uint32_t&>(b);
    }
    char* blk = reinterpret_cast<char*>(g_bbf) + (size_t)(c >> 8) * TILE_BYTES;
    uint32_t r = (uint32_t)(c & 255);
#pragma unroll
    for (int q = 0; q < 8; ++q)
        *reinterpret_cast<uint4*>(blk + SWZ128(r * 128 + q * 16)) = pk[q];
    g_bnorm[c] = n;
}

__global__ void prep_x_kernel(const float* __restrict__ x) {
    int c = blockIdx.x * 256 + threadIdx.x;
    const float4* s = reinterpret_cast<const float4*>(x) + (size_t)c * 16;
    uint4 pk[8];
    uint32_t* pw = reinterpret_cast<uint32_t*>(pk);
    float n = 0.f;
#pragma unroll
    for (int q = 0; q < 16; ++q) {
        float4 v = s[q];
        n = fmaf(v.x, v.x, n); n = fmaf(v.y, v.y, n);
        n = fmaf(v.z, v.z, n); n = fmaf(v.w, v.w, n);
        __nv_bfloat162 a = __floats2bfloat162_rn(v.x, v.y);
        __nv_bfloat162 b = __floats2bfloat162_rn(v.z, v.w);
        pw[2 * q]     = reinterpret_cast<uint32_t&>(a);
        pw[2 * q + 1] = reinterpret_cast<uint32_t&>(b);
    }
    uint4* dst = reinterpret_cast<uint4*>(g_xbf) + (size_t)c * 8;
#pragma unroll
    for (int i = 0; i < 8; ++i) dst[i] = pk[i];
    g_xnorm[c] = n;
}

// ---------------- main fused GEMM + top-k kernel ----------------
extern __shared__ char smem[];

__global__ void __launch_bounds__(THREADS, 1)
pbe_mma_kernel() {
    const int tid  = threadIdx.x;
    const int lane = tid & 31;
    const int w    = tid >> 5;           // 0..15
    const int g    = lane >> 2;          // 0..7
    const int tig  = lane & 3;           // 0..3
    const int part = blockIdx.x;
    const int rt   = blockIdx.y;
    const int cand_base = part * CPART;
    const int row_base  = rt * ROWS_CTA + w * 16;

    const uint32_t sbase = smem_u32(smem);
    const uint32_t mb0   = sbase + SM_MBAR;

    // ---- A fragments: 1 m-block (16 rows) per warp, persistent ----
    uint32_t afr[4][4];
    {
        const uint32_t* x0 = reinterpret_cast<const uint32_t*>(
            g_xbf + (size_t)(row_base + g) * DIM);
        const uint32_t* x1 = reinterpret_cast<const uint32_t*>(
            g_xbf + (size_t)(row_base + g + 8) * DIM);
#pragma unroll
        for (int kc = 0; kc < 4; ++kc) {
            afr[kc][0] = x0[kc * 8 + tig];
            afr[kc][1] = x1[kc * 8 + tig];
            afr[kc][2] = x0[kc * 8 + tig + 4];
            afr[kc][3] = x1[kc * 8 + tig + 4];
        }
    }

    // ---- per-lane ldmatrix offsets: row = cand (lane&7), chunk = lane>>3;
    //      swizzle XOR applied to the FULL chunk offset (incl. +64) so no
    //      carry can leak into the candidate-row bits.
    const uint32_t l8  = (uint32_t)(lane & 7);
    const uint32_t qof = (uint32_t)((lane >> 3) * 16);
    const uint32_t sw  = l8 << 4;
    const uint32_t lm_off0 = l8 * 128 + (qof ^ sw);          // k bytes 0..63
    const uint32_t lm_off1 = l8 * 128 + ((qof + 64) ^ sw);   // k bytes 64..127

    // ---- mbarriers + prologue staging ----
    if (tid == 0) {
        MBARRIER_INIT(mb0 + 0,  1);
        MBARRIER_INIT(mb0 + 8,  1);
        MBARRIER_INIT(mb0 + 16, 1);
    }
    __syncthreads();

    auto issue = [&](int t) {            // thread 0 only
        int s = t % 3;
        uint32_t bar = mb0 + s * 8;
        MBARRIER_EXPECT_TX(bar, TILE_BYTES + BN_BYTES);
        bulk_g2s(sbase + SM_B + s * TILE_BYTES,
                 reinterpret_cast<const char*>(g_bbf)
                   + (size_t)(cand_base + t * TN) * 128,
                 TILE_BYTES, bar);
        bulk_g2s(sbase + SM_BN + s * BN_BYTES,
                 g_bnorm + cand_base + t * TN, BN_BYTES, bar);
    };
    if (tid == 0) { issue(0); issue(1); }

    // ---- top-11 lists for this thread's 2 rows ----
    float h0[KSEL], h1[KSEL];
#pragma unroll
    for (int j = 0; j < KSEL; ++j) { h0[j] = POS_INF; h1[j] = POS_INF; }

    uint32_t ph[3] = {0, 0, 0};

    for (int t = 0; t < NT; ++t) {
        const int slot = t % 3;
        __syncthreads();                 // all warps finished compute(t-1)
        if (t + 2 < NT && tid == 0) issue(t + 2);
        MBARRIER_WAIT_PARITY(mb0 + slot * 8, ph[slot]);
        ph[slot] ^= 1;

        const uint32_t tb0 = sbase + SM_B + slot * TILE_BYTES + lm_off0;
        const uint32_t tb1 = sbase + SM_B + slot * TILE_BYTES + lm_off1;
        const float*   bns = reinterpret_cast<const float*>(
                                 smem + SM_BN + slot * BN_BYTES) + tig * 2;

        // fragments for nb pair p live in f[nb&1][0..7]
        uint32_t fA[2][8], fB[2][8];
        auto load_pair = [&](int p, uint32_t f[2][8]) {
            const uint32_t po = (uint32_t)(p * 2048);
            ldsm4(&f[0][0], tb0 + po);               // nb=2p,   k 0..31
            ldsm4(&f[0][4], tb1 + po);               // nb=2p,   k 32..63
            ldsm4(&f[1][0], tb0 + po + 1024);        // nb=2p+1, k 0..31
            ldsm4(&f[1][4], tb1 + po + 1024);        // nb=2p+1, k 32..63
        };
        load_pair(0, fA);

#pragma unroll
        for (int p = 0; p < 16; ++p) {
            uint32_t (*fc)[8] = (p & 1) ? fB : fA;
            uint32_t (*fn)[8] = (p & 1) ? fA : fB;
            if (p < 15) load_pair(p + 1, fn);

            float acc[2][4];
#pragma unroll
            for (int q = 0; q < 2; ++q) {
                const float2 bnv = *reinterpret_cast<const float2*>(
                    &bns[(p * 2 + q) * 8]);
                acc[q][0] = bnv.x; acc[q][1] = bnv.y;
                acc[q][2] = bnv.x; acc[q][3] = bnv.y;
            }
#pragma unroll
            for (int kc = 0; kc < 4; ++kc) {
                mma16816(acc[0], afr[kc], fc[0][kc * 2], fc[0][kc * 2 + 1]);
                mma16816(acc[1], afr[kc], fc[1][kc * 2], fc[1][kc * 2 + 1]);
            }
            // acc IS the distance (bn - 2*dot); |x|^2 deferred
#pragma unroll
            for (int q = 0; q < 2; ++q) {
                if (fminf(acc[q][0], acc[q][1]) < h0[KSEL - 1]) {
                    if (acc[q][0] < h0[KSEL - 1]) bubble_insert(h0, acc[q][0]);
                    if (acc[q][1] < h0[KSEL - 1]) bubble_insert(h0, acc[q][1]);
                }
                if (fminf(acc[q][2], acc[q][3]) < h1[KSEL - 1]) {
                    if (acc[q][2] < h1[KSEL - 1]) bubble_insert(h1, acc[q][2]);
                    if (acc[q][3] < h1[KSEL - 1]) bubble_insert(h1, acc[q][3]);
                }
            }
        }
    }

    // ---- merge across the 4 tig lanes; tig 0 writes 1 list per row/part ----
    merge11(h0, 1); merge11(h0, 2);
    merge11(h1, 1); merge11(h1, 2);
    if (tig == 0) {
        float* p0 = &g_partial[((size_t)(row_base + g)     * PARTS + part) * KSEL];
        float* p1 = &g_partial[((size_t)(row_base + g + 8) * PARTS + part) * KSEL];
#pragma unroll
        for (int j = 0; j < KSEL; ++j) { p0[j] = h0[j]; p1[j] = h1[j]; }
    }
}

// ---------------- final merge kernel: one warp per row ----------------
__global__ void final_kernel(float* __restrict__ out) {
    const int row  = blockIdx.x * 8 + (threadIdx.x >> 5);
    const int lane = threadIdx.x & 31;
    float h[KSEL];
    if (lane < PARTS) {
        const float* p = &g_partial[((size_t)row * PARTS + lane) * KSEL];
#pragma unroll
        for (int j = 0; j < KSEL; ++j) h[j] = p[j];
    } else {
#pragma unroll
        for (int j = 0; j < KSEL; ++j) h[j] = POS_INF;
    }
    merge11(h, 1); merge11(h, 2); merge11(h, 4); merge11(h, 8);
    if (lane == 0) {
        float xn = g_xnorm[row];
        float s = 0.f;
#pragma unroll
        for (int j = 1; j < KSEL; ++j)          // drop self-match (h[0])
            s += sqrtf(fmaxf(xn + h[j], 0.f));
        out[row] = log1pf(s * (1.f / (KSEL - 1)));
    }
}

// ---------------- launch ----------------
extern "C" void kernel_launch(void* const* d_in, const int* in_sizes, int n_in,
                              void* d_out, int out_size) {
    const float* a = (const float*)d_in[0];
    const float* b = (const float*)d_in[1];
    const float* x = a;
    const float* buf = b;
    if (in_sizes[0] > in_sizes[1]) { x = b; buf = a; }

    cudaFuncSetAttribute(pbe_mma_kernel,
                         cudaFuncAttributeMaxDynamicSharedMemorySize, SMEM_TOTAL);

    prep_buf_kernel<<<M_CANDS / 256, 256>>>(buf);
    prep_x_kernel<<<N_ROWS / 256, 256>>>(x);

    dim3 grid(PARTS, ROWTILES);
    pbe_mma_kernel<<<grid, THREADS, SMEM_TOTAL>>>();

    final_kernel<<<N_ROWS / 8, 256>>>((float*)d_out);
}